// round 16
// baseline (speedup 1.0000x reference)
#include <cuda_runtime.h>
#include <cstdint>

#define NCTA_SM 6
#define NBLK (148 * NCTA_SM)
#define NTHR 128
#define WPB  (NTHR / 32)
#define NWARPS (NBLK * WPB)

static __device__ __forceinline__ float tanh_fast(float x) {
    float r; asm("tanh.approx.f32 %0, %1;" : "=f"(r) : "f"(x)); return r;
}
static __device__ __forceinline__ uint32_t tf32r(float x) {   // f32 -> tf32 (RNA)
    uint32_t r; asm("cvt.rna.tf32.f32 %0, %1;" : "=r"(r) : "f"(x)); return r;
}
// D = A*B + D (accumulate in place)
static __device__ __forceinline__ void mma_tf32(
    float& c0, float& c1, float& c2, float& c3,
    uint32_t a0, uint32_t a1, uint32_t a2, uint32_t a3,
    uint32_t b0, uint32_t b1)
{
    asm volatile(
        "mma.sync.aligned.m16n8k8.row.col.f32.tf32.tf32.f32 "
        "{%0,%1,%2,%3},{%4,%5,%6,%7},{%8,%9},{%0,%1,%2,%3};"
        : "+f"(c0), "+f"(c1), "+f"(c2), "+f"(c3)
        : "r"(a0), "r"(a1), "r"(a2), "r"(a3), "r"(b0), "r"(b1));
}
// D = A*B + C, C given as an already-quad float4 (one aligned LDS.128, no MOVs)
static __device__ __forceinline__ void mma_tf32_c(
    float& d0, float& d1, float& d2, float& d3,
    uint32_t a0, uint32_t a1, uint32_t a2, uint32_t a3,
    uint32_t b0, uint32_t b1, const float4& c)
{
    asm volatile(
        "mma.sync.aligned.m16n8k8.row.col.f32.tf32.tf32.f32 "
        "{%0,%1,%2,%3},{%4,%5,%6,%7},{%8,%9},{%10,%11,%12,%13};"
        : "=f"(d0), "=f"(d1), "=f"(d2), "=f"(d3)
        : "r"(a0), "r"(a1), "r"(a2), "r"(a3), "r"(b0), "r"(b1),
          "f"(c.x), "f"(c.y), "f"(c.z), "f"(c.w));
}
static __device__ __forceinline__ float4 ldx4g(const float* __restrict__ x, int row, int col, int n) {
    if (row < n) return *reinterpret_cast<const float4*>(x + (size_t)row * 16 + col);
    return make_float4(0.0f, 0.0f, 0.0f, 0.0f);
}

// out[i] = relu((1 - sigmoid(x@Wz' + bz')) * tanh(x@Wh' + bh')) @ Wlin + blin
// (H=0 collapses the GRU; edge inputs mathematically unused for ChebConv K=1.)
// TF32 mma.m16n8k8 single product; K permuted so lane t owns feats {4t..4t+3}
// (A frags straight from one LDG.128/row). Bias enters the first MMA of each
// chain as the C operand, loaded as a pre-duplicated quad (z0,z1,z0,z1) via a
// single LDS.128 -> zero accumulator-init MOVs.
// Z-side pre-scaled 0.5: 1-sigmoid(a) = 0.5*(1 - tanh(a')), 0.5 in Wlin.
__global__ void __launch_bounds__(NTHR, NCTA_SM) gru_mma_kernel(
    const float* __restrict__ x,
    const float* __restrict__ Wxz, const float* __restrict__ bxz,
    const float* __restrict__ bhz,
    const float* __restrict__ Wxh, const float* __restrict__ bxh,
    const float* __restrict__ bhh,
    const float* __restrict__ Wlin, const float* __restrict__ blin,
    float* __restrict__ out, int n)
{
    __shared__ uint4  sB[8][32];      // tf32 (W[4t], W[4t+1], W[4t+2], W[4t+3]) at col g
    __shared__ float4 sBiasZ[4][32];  // (z0, z1, z0, z1) quad for chunk pair jp
    __shared__ float4 sBiasH[4][32];  // (h0, h1, h0, h1)
    __shared__ float2 sWl[4][32];     // (wl0, wl1) per chunk pair, 0.5 folded
    __shared__ float  sBl;

    const int lane = threadIdx.x & 31;
    const int wid  = threadIdx.x >> 5;
    const int g    = lane >> 2;
    const int t    = lane & 3;

    // ---- warp 0: stage lane-indexed constants ------------------------------
    if (wid == 0) {
#pragma unroll
        for (int j = 0; j < 8; j++) {
            const bool zside = (j < 4);
            const float sc = zside ? 0.5f : 1.0f;
            const float* W = zside ? Wxz : Wxh;
            const int c = zside ? (8 * j + g) : (8 * (j - 4) + g);
            sB[j][lane] = make_uint4(
                tf32r(sc * __ldg(&W[(4 * t)     * 32 + c])),
                tf32r(sc * __ldg(&W[(4 * t + 1) * 32 + c])),
                tf32r(sc * __ldg(&W[(4 * t + 2) * 32 + c])),
                tf32r(sc * __ldg(&W[(4 * t + 3) * 32 + c])));
        }
#pragma unroll
        for (int j = 0; j < 4; j++) {
            const int zc = 8 * j + 2 * t;
            const float z0 = 0.5f * (__ldg(&bxz[zc])     + __ldg(&bhz[zc]));
            const float z1 = 0.5f * (__ldg(&bxz[zc + 1]) + __ldg(&bhz[zc + 1]));
            const float h0 = __ldg(&bxh[zc])     + __ldg(&bhh[zc]);
            const float h1 = __ldg(&bxh[zc + 1]) + __ldg(&bhh[zc + 1]);
            sBiasZ[j][lane] = make_float4(z0, z1, z0, z1);
            sBiasH[j][lane] = make_float4(h0, h1, h0, h1);
            sWl[j][lane] = make_float2(0.5f * __ldg(&Wlin[zc]),
                                       0.5f * __ldg(&Wlin[zc + 1]));
        }
        if (lane == 0) sBl = __ldg(&blin[0]);
    }
    __syncthreads();

    const int nt32 = (n + 31) >> 5;               // 32-node tiles
    const bool aligned = (n & 31) == 0;           // bench: n = 1M -> true
    int tile = blockIdx.x * WPB + wid;
    if (tile >= nt32) return;

    const float bl = sBl;
    const long long step = (long long)NWARPS * 512;
    const float* p = x + (size_t)tile * 512 + (size_t)(g * 16 + 4 * t);

    // one LDG.128 per row: rows {g, g+8} (set A), {g+16, g+24} (set B)
    float4 vA0, vA1, vB0, vB1;
    if (aligned || tile * 32 + 32 <= n) {
        vA0 = *(const float4*)(p);
        vA1 = *(const float4*)(p + 128);
        vB0 = *(const float4*)(p + 256);
        vB1 = *(const float4*)(p + 384);
    } else {
        const int b = tile * 32;
        vA0 = ldx4g(x, b + g,      4 * t, n);
        vA1 = ldx4g(x, b + g + 8,  4 * t, n);
        vB0 = ldx4g(x, b + g + 16, 4 * t, n);
        vB1 = ldx4g(x, b + g + 24, 4 * t, n);
    }

#pragma unroll 1
    while (true) {
        // A fragments (tf32): chunk0 = feats (4t, 4t+1), chunk1 = (4t+2, 4t+3)
        const uint32_t aA00 = tf32r(vA0.x), aA01 = tf32r(vA1.x);
        const uint32_t aA02 = tf32r(vA0.y), aA03 = tf32r(vA1.y);
        const uint32_t aA10 = tf32r(vA0.z), aA11 = tf32r(vA1.z);
        const uint32_t aA12 = tf32r(vA0.w), aA13 = tf32r(vA1.w);
        const uint32_t aB00 = tf32r(vB0.x), aB01 = tf32r(vB1.x);
        const uint32_t aB02 = tf32r(vB0.y), aB03 = tf32r(vB1.y);
        const uint32_t aB10 = tf32r(vB0.z), aB11 = tf32r(vB1.z);
        const uint32_t aB12 = tf32r(vB0.w), aB13 = tf32r(vB1.w);

        const int node0 = tile * 32 + g;
        const int tnext = tile + NWARPS;
        const bool hasnext = (tnext < nt32);
        if (hasnext) {                      // prefetch next tile under MMA+epilogue
            p += step;
            if (aligned || tnext * 32 + 32 <= n) {
                vA0 = *(const float4*)(p);
                vA1 = *(const float4*)(p + 128);
                vB0 = *(const float4*)(p + 256);
                vB1 = *(const float4*)(p + 384);
            } else {
                const int b = tnext * 32;
                vA0 = ldx4g(x, b + g,      4 * t, n);
                vA1 = ldx4g(x, b + g + 8,  4 * t, n);
                vB0 = ldx4g(x, b + g + 16, 4 * t, n);
                vB1 = ldx4g(x, b + g + 24, 4 * t, n);
            }
        }

        float r0 = 0.0f, r1 = 0.0f, r2 = 0.0f, r3 = 0.0f;
#pragma unroll
        for (int jp = 0; jp < 4; jp++) {
            const uint4  bz  = sB[jp][lane];       // Z-side W (chunk0: x,y; chunk1: z,w)
            const uint4  bh  = sB[jp + 4][lane];   // H-side W
            const float4 bqz = sBiasZ[jp][lane];   // bias quads (LDS.128 -> C operand)
            const float4 bqh = sBiasH[jp][lane];
            const float2 w   = sWl[jp][lane];

            float zA0, zA1, zA2, zA3, hA0, hA1, hA2, hA3;
            float zB0, zB1, zB2, zB3, hB0, hB1, hB2, hB3;

            // chunk0: D = A*B + bias-quad (no init MOVs); chunk1: accumulate
            mma_tf32_c(zA0, zA1, zA2, zA3, aA00, aA01, aA02, aA03, bz.x, bz.y, bqz);
            mma_tf32_c(zB0, zB1, zB2, zB3, aB00, aB01, aB02, aB03, bz.x, bz.y, bqz);
            mma_tf32_c(hA0, hA1, hA2, hA3, aA00, aA01, aA02, aA03, bh.x, bh.y, bqh);
            mma_tf32_c(hB0, hB1, hB2, hB3, aB00, aB01, aB02, aB03, bh.x, bh.y, bqh);
            mma_tf32(zA0, zA1, zA2, zA3, aA10, aA11, aA12, aA13, bz.z, bz.w);
            mma_tf32(zB0, zB1, zB2, zB3, aB10, aB11, aB12, aB13, bz.z, bz.w);
            mma_tf32(hA0, hA1, hA2, hA3, aA10, aA11, aA12, aA13, bh.z, bh.w);
            mma_tf32(hB0, hB1, hB2, hB3, aB10, aB11, aB12, aB13, bh.z, bh.w);

            // epilogue: p = (1 - tanh(z')) * tanh(h'), 0.5 folded into wlin
            float t1, t2, pp;
            t1 = tanh_fast(zA0); t2 = tanh_fast(hA0);
            pp = t2 - t1 * t2; r0 = fmaf(fmaxf(pp, 0.0f), w.x, r0);
            t1 = tanh_fast(zA1); t2 = tanh_fast(hA1);
            pp = t2 - t1 * t2; r0 = fmaf(fmaxf(pp, 0.0f), w.y, r0);
            t1 = tanh_fast(zA2); t2 = tanh_fast(hA2);
            pp = t2 - t1 * t2; r1 = fmaf(fmaxf(pp, 0.0f), w.x, r1);
            t1 = tanh_fast(zA3); t2 = tanh_fast(hA3);
            pp = t2 - t1 * t2; r1 = fmaf(fmaxf(pp, 0.0f), w.y, r1);
            t1 = tanh_fast(zB0); t2 = tanh_fast(hB0);
            pp = t2 - t1 * t2; r2 = fmaf(fmaxf(pp, 0.0f), w.x, r2);
            t1 = tanh_fast(zB1); t2 = tanh_fast(hB1);
            pp = t2 - t1 * t2; r2 = fmaf(fmaxf(pp, 0.0f), w.y, r2);
            t1 = tanh_fast(zB2); t2 = tanh_fast(hB2);
            pp = t2 - t1 * t2; r3 = fmaf(fmaxf(pp, 0.0f), w.x, r3);
            t1 = tanh_fast(zB3); t2 = tanh_fast(hB3);
            pp = t2 - t1 * t2; r3 = fmaf(fmaxf(pp, 0.0f), w.y, r3);
        }

        r0 += __shfl_xor_sync(0xFFFFFFFFu, r0, 1);
        r0 += __shfl_xor_sync(0xFFFFFFFFu, r0, 2);
        r1 += __shfl_xor_sync(0xFFFFFFFFu, r1, 1);
        r1 += __shfl_xor_sync(0xFFFFFFFFu, r1, 2);
        r2 += __shfl_xor_sync(0xFFFFFFFFu, r2, 1);
        r2 += __shfl_xor_sync(0xFFFFFFFFu, r2, 2);
        r3 += __shfl_xor_sync(0xFFFFFFFFu, r3, 1);
        r3 += __shfl_xor_sync(0xFFFFFFFFu, r3, 2);
        if (t == 0) {
            if (aligned) {       // n % 32 == 0: all four rows in range
                out[node0]      = r0 + bl;
                out[node0 + 8]  = r1 + bl;
                out[node0 + 16] = r2 + bl;
                out[node0 + 24] = r3 + bl;
            } else {
                if (node0 < n)      out[node0]      = r0 + bl;
                if (node0 + 8 < n)  out[node0 + 8]  = r1 + bl;
                if (node0 + 16 < n) out[node0 + 16] = r2 + bl;
                if (node0 + 24 < n) out[node0 + 24] = r3 + bl;
            }
        }

        if (!hasnext) break;
        tile = tnext;
    }
}

extern "C" void kernel_launch(void* const* d_in, const int* in_sizes, int n_in,
                              void* d_out, int out_size)
{
    // 0=x, 1=edge_index(unused), 2=edge_weight(unused), 3=Wxz, 4=bxz, 5=Whz(u), 6=bhz,
    // 7=Wxr(u), 8=bxr(u), 9=Whr(u), 10=bhr(u), 11=Wxh, 12=bxh, 13=Whh(u), 14=bhh,
    // 15=Wlin, 16=blin
    const float* x    = (const float*)d_in[0];
    const float* Wxz  = (const float*)d_in[3];
    const float* bxz  = (const float*)d_in[4];
    const float* bhz  = (const float*)d_in[6];
    const float* Wxh  = (const float*)d_in[11];
    const float* bxh  = (const float*)d_in[12];
    const float* bhh  = (const float*)d_in[14];
    const float* Wlin = (const float*)d_in[15];
    const float* blin = (const float*)d_in[16];

    const int n = in_sizes[0] / 16;
    gru_mma_kernel<<<NBLK, NTHR>>>(x, Wxz, bxz, bhz, Wxh, bxh, bhh,
                                   Wlin, blin, (float*)d_out, n);
}

// round 17
// speedup vs baseline: 1.0013x; 1.0013x over previous
#include <cuda_runtime.h>
#include <cstdint>

#define NCTA_SM 6
#define NBLK (148 * NCTA_SM)
#define NTHR 128
#define WPB  (NTHR / 32)
#define NWARPS (NBLK * WPB)

static __device__ __forceinline__ uint32_t tf32r(float x) {   // f32 -> tf32 (RNA)
    uint32_t r; asm("cvt.rna.tf32.f32 %0, %1;" : "=r"(r) : "f"(x)); return r;
}
// pack two f32 -> f16x2 (first arg = high half)
static __device__ __forceinline__ uint32_t pkh2(float hi, float lo) {
    uint32_t r; asm("cvt.rn.f16x2.f32 %0, %1, %2;" : "=r"(r) : "f"(hi), "f"(lo)); return r;
}
static __device__ __forceinline__ uint32_t tanh_h2(uint32_t v) {
    uint32_t r; asm("tanh.approx.f16x2 %0, %1;" : "=r"(r) : "r"(v)); return r;
}
static __device__ __forceinline__ uint32_t mul_h2(uint32_t a, uint32_t b) {
    uint32_t r; asm("mul.rn.f16x2 %0, %1, %2;" : "=r"(r) : "r"(a), "r"(b)); return r;
}
static __device__ __forceinline__ uint32_t sub_h2(uint32_t a, uint32_t b) {
    uint32_t r; asm("sub.rn.f16x2 %0, %1, %2;" : "=r"(r) : "r"(a), "r"(b)); return r;
}
static __device__ __forceinline__ uint32_t relu_h2(uint32_t a) {
    uint32_t r; asm("max.f16x2 %0, %1, %2;" : "=r"(r) : "r"(a), "r"(0u)); return r;
}
static __device__ __forceinline__ void uph2(uint32_t v, float& lo, float& hi) {
    asm("{ .reg .b16 l, h; mov.b32 {l, h}, %2; cvt.f32.f16 %0, l; cvt.f32.f16 %1, h; }"
        : "=f"(lo), "=f"(hi) : "r"(v));
}
// D = A*B + D (accumulate in place)
static __device__ __forceinline__ void mma_tf32(
    float& c0, float& c1, float& c2, float& c3,
    uint32_t a0, uint32_t a1, uint32_t a2, uint32_t a3,
    uint32_t b0, uint32_t b1)
{
    asm volatile(
        "mma.sync.aligned.m16n8k8.row.col.f32.tf32.tf32.f32 "
        "{%0,%1,%2,%3},{%4,%5,%6,%7},{%8,%9},{%0,%1,%2,%3};"
        : "+f"(c0), "+f"(c1), "+f"(c2), "+f"(c3)
        : "r"(a0), "r"(a1), "r"(a2), "r"(a3), "r"(b0), "r"(b1));
}
// D = A*B + C, C given as an already-quad float4 (one aligned LDS.128, no MOVs)
static __device__ __forceinline__ void mma_tf32_c(
    float& d0, float& d1, float& d2, float& d3,
    uint32_t a0, uint32_t a1, uint32_t a2, uint32_t a3,
    uint32_t b0, uint32_t b1, const float4& c)
{
    asm volatile(
        "mma.sync.aligned.m16n8k8.row.col.f32.tf32.tf32.f32 "
        "{%0,%1,%2,%3},{%4,%5,%6,%7},{%8,%9},{%10,%11,%12,%13};"
        : "=f"(d0), "=f"(d1), "=f"(d2), "=f"(d3)
        : "r"(a0), "r"(a1), "r"(a2), "r"(a3), "r"(b0), "r"(b1),
          "f"(c.x), "f"(c.y), "f"(c.z), "f"(c.w));
}
static __device__ __forceinline__ float4 ldx4g(const float* __restrict__ x, int row, int col, int n) {
    if (row < n) return *reinterpret_cast<const float4*>(x + (size_t)row * 16 + col);
    return make_float4(0.0f, 0.0f, 0.0f, 0.0f);
}

// out[i] = relu((1 - sigmoid(x@Wz' + bz')) * tanh(x@Wh' + bh')) @ Wlin + blin
// (H=0 collapses the GRU; edge inputs mathematically unused for ChebConv K=1.)
// TF32 mma.m16n8k8 single product; K permuted so lane t owns feats {4t..4t+3}
// (A frags straight from one LDG.128/row). Bias enters chunk-0 MMAs as a
// pre-duplicated C quad. Epilogue fully packed f16x2: tanh.approx.f16x2 for
// BOTH gates (error calibrated ~4.2e-4 total), gate product + relu in f16x2,
// widen once for the Wlin dot. Z-side pre-scaled 0.5; the 0.5 is in Wlin.
__global__ void __launch_bounds__(NTHR, NCTA_SM) gru_mma_kernel(
    const float* __restrict__ x,
    const float* __restrict__ Wxz, const float* __restrict__ bxz,
    const float* __restrict__ bhz,
    const float* __restrict__ Wxh, const float* __restrict__ bxh,
    const float* __restrict__ bhh,
    const float* __restrict__ Wlin, const float* __restrict__ blin,
    float* __restrict__ out, int n)
{
    __shared__ uint4  sB[8][32];      // tf32 (W[4t], W[4t+1], W[4t+2], W[4t+3]) at col g
    __shared__ float4 sBiasZ[4][32];  // (z0, z1, z0, z1) quad for chunk pair jp
    __shared__ float4 sBiasH[4][32];  // (h0, h1, h0, h1)
    __shared__ float2 sWl[4][32];     // (wl0, wl1) per chunk pair, 0.5 folded
    __shared__ float  sBl;

    const int lane = threadIdx.x & 31;
    const int wid  = threadIdx.x >> 5;
    const int g    = lane >> 2;
    const int t    = lane & 3;

    // ---- warp 0: stage lane-indexed constants ------------------------------
    if (wid == 0) {
#pragma unroll
        for (int j = 0; j < 8; j++) {
            const bool zside = (j < 4);
            const float sc = zside ? 0.5f : 1.0f;
            const float* W = zside ? Wxz : Wxh;
            const int c = zside ? (8 * j + g) : (8 * (j - 4) + g);
            sB[j][lane] = make_uint4(
                tf32r(sc * __ldg(&W[(4 * t)     * 32 + c])),
                tf32r(sc * __ldg(&W[(4 * t + 1) * 32 + c])),
                tf32r(sc * __ldg(&W[(4 * t + 2) * 32 + c])),
                tf32r(sc * __ldg(&W[(4 * t + 3) * 32 + c])));
        }
#pragma unroll
        for (int j = 0; j < 4; j++) {
            const int zc = 8 * j + 2 * t;
            const float z0 = 0.5f * (__ldg(&bxz[zc])     + __ldg(&bhz[zc]));
            const float z1 = 0.5f * (__ldg(&bxz[zc + 1]) + __ldg(&bhz[zc + 1]));
            const float h0 = __ldg(&bxh[zc])     + __ldg(&bhh[zc]);
            const float h1 = __ldg(&bxh[zc + 1]) + __ldg(&bhh[zc + 1]);
            sBiasZ[j][lane] = make_float4(z0, z1, z0, z1);
            sBiasH[j][lane] = make_float4(h0, h1, h0, h1);
            sWl[j][lane] = make_float2(0.5f * __ldg(&Wlin[zc]),
                                       0.5f * __ldg(&Wlin[zc + 1]));
        }
        if (lane == 0) sBl = __ldg(&blin[0]);
    }
    __syncthreads();

    const int nt32 = (n + 31) >> 5;               // 32-node tiles
    const bool aligned = (n & 31) == 0;           // bench: n = 1M -> true
    int tile = blockIdx.x * WPB + wid;
    if (tile >= nt32) return;

    const float bl = sBl;
    const long long step = (long long)NWARPS * 512;
    const float* p = x + (size_t)tile * 512 + (size_t)(g * 16 + 4 * t);

    // one LDG.128 per row: rows {g, g+8} (set A), {g+16, g+24} (set B)
    float4 vA0, vA1, vB0, vB1;
    if (aligned || tile * 32 + 32 <= n) {
        vA0 = *(const float4*)(p);
        vA1 = *(const float4*)(p + 128);
        vB0 = *(const float4*)(p + 256);
        vB1 = *(const float4*)(p + 384);
    } else {
        const int b = tile * 32;
        vA0 = ldx4g(x, b + g,      4 * t, n);
        vA1 = ldx4g(x, b + g + 8,  4 * t, n);
        vB0 = ldx4g(x, b + g + 16, 4 * t, n);
        vB1 = ldx4g(x, b + g + 24, 4 * t, n);
    }

#pragma unroll 1
    while (true) {
        // A fragments (tf32): chunk0 = feats (4t, 4t+1), chunk1 = (4t+2, 4t+3)
        const uint32_t aA00 = tf32r(vA0.x), aA01 = tf32r(vA1.x);
        const uint32_t aA02 = tf32r(vA0.y), aA03 = tf32r(vA1.y);
        const uint32_t aA10 = tf32r(vA0.z), aA11 = tf32r(vA1.z);
        const uint32_t aA12 = tf32r(vA0.w), aA13 = tf32r(vA1.w);
        const uint32_t aB00 = tf32r(vB0.x), aB01 = tf32r(vB1.x);
        const uint32_t aB02 = tf32r(vB0.y), aB03 = tf32r(vB1.y);
        const uint32_t aB10 = tf32r(vB0.z), aB11 = tf32r(vB1.z);
        const uint32_t aB12 = tf32r(vB0.w), aB13 = tf32r(vB1.w);

        const int node0 = tile * 32 + g;
        const int tnext = tile + NWARPS;
        const bool hasnext = (tnext < nt32);
        if (hasnext) {                      // prefetch next tile under MMA+epilogue
            p += step;
            if (aligned || tnext * 32 + 32 <= n) {
                vA0 = *(const float4*)(p);
                vA1 = *(const float4*)(p + 128);
                vB0 = *(const float4*)(p + 256);
                vB1 = *(const float4*)(p + 384);
            } else {
                const int b = tnext * 32;
                vA0 = ldx4g(x, b + g,      4 * t, n);
                vA1 = ldx4g(x, b + g + 8,  4 * t, n);
                vB0 = ldx4g(x, b + g + 16, 4 * t, n);
                vB1 = ldx4g(x, b + g + 24, 4 * t, n);
            }
        }

        float r0 = 0.0f, r1 = 0.0f, r2 = 0.0f, r3 = 0.0f;
#pragma unroll
        for (int jp = 0; jp < 4; jp++) {
            const uint4  bz  = sB[jp][lane];       // Z-side W (chunk0: x,y; chunk1: z,w)
            const uint4  bh  = sB[jp + 4][lane];   // H-side W
            const float4 bqz = sBiasZ[jp][lane];   // bias quads (LDS.128 -> C operand)
            const float4 bqh = sBiasH[jp][lane];
            const float2 w   = sWl[jp][lane];

            float zA0, zA1, zA2, zA3, hA0, hA1, hA2, hA3;
            float zB0, zB1, zB2, zB3, hB0, hB1, hB2, hB3;

            // chunk0: D = A*B + bias-quad; chunk1: accumulate
            mma_tf32_c(zA0, zA1, zA2, zA3, aA00, aA01, aA02, aA03, bz.x, bz.y, bqz);
            mma_tf32_c(zB0, zB1, zB2, zB3, aB00, aB01, aB02, aB03, bz.x, bz.y, bqz);
            mma_tf32_c(hA0, hA1, hA2, hA3, aA00, aA01, aA02, aA03, bh.x, bh.y, bqh);
            mma_tf32_c(hB0, hB1, hB2, hB3, aB00, aB01, aB02, aB03, bh.x, bh.y, bqh);
            mma_tf32(zA0, zA1, zA2, zA3, aA10, aA11, aA12, aA13, bz.z, bz.w);
            mma_tf32(zB0, zB1, zB2, zB3, aB10, aB11, aB12, aB13, bz.z, bz.w);
            mma_tf32(hA0, hA1, hA2, hA3, aA10, aA11, aA12, aA13, bh.z, bh.w);
            mma_tf32(hB0, hB1, hB2, hB3, aB10, aB11, aB12, aB13, bh.z, bh.w);

            // packed f16x2 gates: t1 = tanh(z'), t2 = tanh(h');
            // pp = relu(t2 - t1*t2); out += pp . wlin (0.5 pre-folded)
            const uint32_t t1q0 = tanh_h2(pkh2(zA1, zA0));
            const uint32_t t1q1 = tanh_h2(pkh2(zA3, zA2));
            const uint32_t t1q2 = tanh_h2(pkh2(zB1, zB0));
            const uint32_t t1q3 = tanh_h2(pkh2(zB3, zB2));
            const uint32_t t2q0 = tanh_h2(pkh2(hA1, hA0));
            const uint32_t t2q1 = tanh_h2(pkh2(hA3, hA2));
            const uint32_t t2q2 = tanh_h2(pkh2(hB1, hB0));
            const uint32_t t2q3 = tanh_h2(pkh2(hB3, hB2));

            const uint32_t pp0 = relu_h2(sub_h2(t2q0, mul_h2(t1q0, t2q0)));
            const uint32_t pp1 = relu_h2(sub_h2(t2q1, mul_h2(t1q1, t2q1)));
            const uint32_t pp2 = relu_h2(sub_h2(t2q2, mul_h2(t1q2, t2q2)));
            const uint32_t pp3 = relu_h2(sub_h2(t2q3, mul_h2(t1q3, t2q3)));

            float plo, phi;
            uph2(pp0, plo, phi); r0 = fmaf(plo, w.x, r0); r0 = fmaf(phi, w.y, r0);
            uph2(pp1, plo, phi); r1 = fmaf(plo, w.x, r1); r1 = fmaf(phi, w.y, r1);
            uph2(pp2, plo, phi); r2 = fmaf(plo, w.x, r2); r2 = fmaf(phi, w.y, r2);
            uph2(pp3, plo, phi); r3 = fmaf(plo, w.x, r3); r3 = fmaf(phi, w.y, r3);
        }

        r0 += __shfl_xor_sync(0xFFFFFFFFu, r0, 1);
        r0 += __shfl_xor_sync(0xFFFFFFFFu, r0, 2);
        r1 += __shfl_xor_sync(0xFFFFFFFFu, r1, 1);
        r1 += __shfl_xor_sync(0xFFFFFFFFu, r1, 2);
        r2 += __shfl_xor_sync(0xFFFFFFFFu, r2, 1);
        r2 += __shfl_xor_sync(0xFFFFFFFFu, r2, 2);
        r3 += __shfl_xor_sync(0xFFFFFFFFu, r3, 1);
        r3 += __shfl_xor_sync(0xFFFFFFFFu, r3, 2);
        if (t == 0) {
            if (aligned) {       // n % 32 == 0: all four rows in range
                out[node0]      = r0 + bl;
                out[node0 + 8]  = r1 + bl;
                out[node0 + 16] = r2 + bl;
                out[node0 + 24] = r3 + bl;
            } else {
                if (node0 < n)      out[node0]      = r0 + bl;
                if (node0 + 8 < n)  out[node0 + 8]  = r1 + bl;
                if (node0 + 16 < n) out[node0 + 16] = r2 + bl;
                if (node0 + 24 < n) out[node0 + 24] = r3 + bl;
            }
        }

        if (!hasnext) break;
        tile = tnext;
    }
}

extern "C" void kernel_launch(void* const* d_in, const int* in_sizes, int n_in,
                              void* d_out, int out_size)
{
    // 0=x, 1=edge_index(unused), 2=edge_weight(unused), 3=Wxz, 4=bxz, 5=Whz(u), 6=bhz,
    // 7=Wxr(u), 8=bxr(u), 9=Whr(u), 10=bhr(u), 11=Wxh, 12=bxh, 13=Whh(u), 14=bhh,
    // 15=Wlin, 16=blin
    const float* x    = (const float*)d_in[0];
    const float* Wxz  = (const float*)d_in[3];
    const float* bxz  = (const float*)d_in[4];
    const float* bhz  = (const float*)d_in[6];
    const float* Wxh  = (const float*)d_in[11];
    const float* bxh  = (const float*)d_in[12];
    const float* bhh  = (const float*)d_in[14];
    const float* Wlin = (const float*)d_in[15];
    const float* blin = (const float*)d_in[16];

    const int n = in_sizes[0] / 16;
    gru_mma_kernel<<<NBLK, NTHR>>>(x, Wxz, bxz, bhz, Wxh, bxh, bhh,
                                   Wlin, blin, (float*)d_out, n);
}